// round 17
// baseline (speedup 1.0000x reference)
#include <cuda_runtime.h>
#include <cuda_fp16.h>
#include <cstddef>

#define NUM_USERS 200000
#define NUM_ITEMS 100000
#define N_NODES   (NUM_USERS + NUM_ITEMS)
#define DIM       64
#define NNZ       4000000

#define SCAN_TPB  1024
#define NB_SCAN   ((N_NODES + SCAN_TPB - 1) / SCAN_TPB)   // 293

#define FLAG_AGG    (1 << 30)
#define FLAG_PREFIX (2 << 30)
#define VAL_MASK    ((1 << 30) - 1)

// Scratch (allocation in kernel_launch is forbidden).
__device__ __half g_h0[(size_t)N_NODES * DIM];
__device__ __half g_h1[(size_t)N_NODES * DIM];
__device__ __half g_h2[(size_t)N_NODES * DIM];
__device__ __align__(16) int2 g_edges[NNZ];   // (col, val-bits), row-sorted
__device__ int    g_cnt[N_NODES];
__device__ int    g_row_ptr[N_NODES + 1];
__device__ int    g_tile_status[NB_SCAN];

// ---------------------------------------------------------------------------
// fused init + hist:
//   h0 = fp16(concat(user_emb, item_emb))           (threads < nf4)
//   cnt[rows[e]]++ for 4 edges per thread           (threads < NNZ/4)
// ---------------------------------------------------------------------------
__global__ void init_hist_kernel(const float* __restrict__ ue,
                                 const float* __restrict__ ie,
                                 __half* __restrict__ h0,
                                 const int* __restrict__ rows,
                                 int* __restrict__ cnt) {
    size_t t = (size_t)blockIdx.x * blockDim.x + threadIdx.x;
    const size_t nf4 = (size_t)N_NODES * DIM / 4;
    if (t < nf4) {
        const size_t uf4 = (size_t)NUM_USERS * DIM / 4;
        float4 v;
        if (t < uf4) v = ((const float4*)ue)[t];
        else         v = ((const float4*)ie)[t - uf4];
        __half2 lo = __float22half2_rn(make_float2(v.x, v.y));
        __half2 hi = __float22half2_rn(make_float2(v.z, v.w));
        ((__half2*)h0)[t * 2]     = lo;
        ((__half2*)h0)[t * 2 + 1] = hi;
    }
    if (t < NNZ / 4) {
        int4 r = __ldg((const int4*)(rows + t * 4));
        atomicAdd(&cnt[r.x], 1);
        atomicAdd(&cnt[r.y], 1);
        atomicAdd(&cnt[r.z], 1);
        atomicAdd(&cnt[r.w], 1);
    }
}

// ---------------------------------------------------------------------------
// single-pass decoupled-lookback exclusive scan: row_ptr = exscan(cnt)
// tile_status must be zeroed before launch. cnt is left intact (used as a
// countdown cursor by scatter_sort).
// ---------------------------------------------------------------------------
__global__ void __launch_bounds__(SCAN_TPB)
scan_rowptr_kernel(const int* __restrict__ cnt,
                   int* __restrict__ row_ptr,
                   int* __restrict__ tile_status) {
    __shared__ int wsum[32];
    __shared__ int s_prefix;
    int b = blockIdx.x;
    int i = b * SCAN_TPB + threadIdx.x;
    int lane = threadIdx.x & 31;
    int wid  = threadIdx.x >> 5;

    int v = (i < N_NODES) ? cnt[i] : 0;
    int s = v;
#pragma unroll
    for (int off = 1; off < 32; off <<= 1) {
        int t = __shfl_up_sync(0xffffffffu, s, off);
        if (lane >= off) s += t;
    }
    if (lane == 31) wsum[wid] = s;
    __syncthreads();
    if (wid == 0) {
        int ws = wsum[lane];
#pragma unroll
        for (int off = 1; off < 32; off <<= 1) {
            int t = __shfl_up_sync(0xffffffffu, ws, off);
            if (lane >= off) ws += t;
        }
        wsum[lane] = ws;
    }
    __syncthreads();
    int wbase = (wid > 0) ? wsum[wid - 1] : 0;
    int incl  = wbase + s;            // block-inclusive prefix
    int total = wsum[31];             // block aggregate

    if (threadIdx.x == 0) {
        if (b == 0) {
            atomicExch(&tile_status[0], total | FLAG_PREFIX);
            s_prefix = 0;
        } else {
            atomicExch(&tile_status[b], total | FLAG_AGG);
            int ex = 0;
            int p = b - 1;
            while (true) {
                int st = atomicAdd(&tile_status[p], 0);
                int flag = st & ~VAL_MASK;
                if (flag == 0) continue;              // not published yet
                ex += st & VAL_MASK;
                if (flag == FLAG_PREFIX) break;
                --p;
            }
            atomicExch(&tile_status[b], (ex + total) | FLAG_PREFIX);
            s_prefix = ex;
        }
    }
    __syncthreads();
    int ex = s_prefix;
    if (i < N_NODES) row_ptr[i] = ex + incl - v;      // exclusive
    if (i == N_NODES - 1) row_ptr[N_NODES] = ex + incl;   // == NNZ
}

// ---------------------------------------------------------------------------
// Permute edges into row-sorted order, 4 edges per thread.
// cnt (degrees) is consumed as a countdown cursor.
// ---------------------------------------------------------------------------
__global__ void scatter_sort_kernel(const float* __restrict__ vals,
                                    const int*   __restrict__ rows,
                                    const int*   __restrict__ cols,
                                    const int*   __restrict__ row_ptr,
                                    int*         __restrict__ cnt,
                                    int2*        __restrict__ edges) {
    int t = blockIdx.x * blockDim.x + threadIdx.x;
    int e = t * 4;
    if (e + 3 < NNZ) {
        int4   r = __ldg((const int4*)(rows + e));
        int4   c = __ldg((const int4*)(cols + e));
        float4 v = __ldg((const float4*)(vals + e));
        int p0 = __ldg(row_ptr + r.x) + atomicAdd(&cnt[r.x], -1) - 1;
        edges[p0] = make_int2(c.x, __float_as_int(v.x));
        int p1 = __ldg(row_ptr + r.y) + atomicAdd(&cnt[r.y], -1) - 1;
        edges[p1] = make_int2(c.y, __float_as_int(v.y));
        int p2 = __ldg(row_ptr + r.z) + atomicAdd(&cnt[r.z], -1) - 1;
        edges[p2] = make_int2(c.z, __float_as_int(v.z));
        int p3 = __ldg(row_ptr + r.w) + atomicAdd(&cnt[r.w], -1) - 1;
        edges[p3] = make_int2(c.w, __float_as_int(v.w));
    } else {
        for (int k = e; k < NNZ; ++k) {
            int r = rows[k];
            int p = __ldg(row_ptr + r) + atomicAdd(&cnt[r], -1) - 1;
            edges[p] = make_int2(cols[k], __float_as_int(vals[k]));
        }
    }
}

// ---------------------------------------------------------------------------
// spmm core: one warp per row; 16 lanes per edge -> TWO edges per gather LDG.
// 8 edges/iteration: 4 int4 edge loads, then 4 independent paired gathers.
// ---------------------------------------------------------------------------
__device__ __forceinline__ void fetch_acc(const __half* __restrict__ x,
                                          int c, float v, int sub, float4& acc) {
    uint2 d = __ldg((const uint2*)(x + (size_t)c * DIM) + sub);
    float2 lo = __half22float2(*(const __half2*)&d.x);
    float2 hi = __half22float2(*(const __half2*)&d.y);
    acc.x += v * lo.x;
    acc.y += v * lo.y;
    acc.z += v * hi.x;
    acc.w += v * hi.y;
}

__device__ __forceinline__ void pair_acc(const __half* __restrict__ x,
                                         int4 E, int half, int sub, float4& acc) {
    int   c = half ? E.z : E.x;
    float v = __int_as_float(half ? E.w : E.y);
    fetch_acc(x, c, v, sub, acc);
}

__device__ __forceinline__ float4 row_accumulate(const int2* __restrict__ edges,
                                                 const __half* __restrict__ x,
                                                 int s, int e, int half, int sub) {
    float4 acc = make_float4(0.f, 0.f, 0.f, 0.f);
    int i = s;
    if ((i & 1) && i < e) {           // head peel to even index
        int2 E = __ldg(edges + i);
        float v = half ? 0.f : __int_as_float(E.y);
        fetch_acc(x, E.x, v, sub, acc);
        ++i;
    }
    for (; i + 7 < e; i += 8) {
        int4 E0 = __ldg((const int4*)(edges + i));
        int4 E1 = __ldg((const int4*)(edges + i + 2));
        int4 E2 = __ldg((const int4*)(edges + i + 4));
        int4 E3 = __ldg((const int4*)(edges + i + 6));
        pair_acc(x, E0, half, sub, acc);
        pair_acc(x, E1, half, sub, acc);
        pair_acc(x, E2, half, sub, acc);
        pair_acc(x, E3, half, sub, acc);
    }
    for (; i + 3 < e; i += 4) {
        int4 E0 = __ldg((const int4*)(edges + i));
        int4 E1 = __ldg((const int4*)(edges + i + 2));
        pair_acc(x, E0, half, sub, acc);
        pair_acc(x, E1, half, sub, acc);
    }
    for (; i + 1 < e; i += 2) {
        int4 E0 = __ldg((const int4*)(edges + i));
        pair_acc(x, E0, half, sub, acc);
    }
    if (i < e) {
        int2 E = __ldg(edges + i);
        float v = half ? 0.f : __int_as_float(E.y);
        fetch_acc(x, E.x, v, sub, acc);
    }
    // merge the two edge-halves (lane l += lane l^16)
    acc.x += __shfl_xor_sync(0xffffffffu, acc.x, 16);
    acc.y += __shfl_xor_sync(0xffffffffu, acc.y, 16);
    acc.z += __shfl_xor_sync(0xffffffffu, acc.z, 16);
    acc.w += __shfl_xor_sync(0xffffffffu, acc.w, 16);
    return acc;
}

// layer 1 & 2: y = A * x (fp16 out)
__global__ void __launch_bounds__(256)
spmm_h_kernel(const int*    __restrict__ row_ptr,
              const int2*   __restrict__ edges,
              const __half* __restrict__ x,
              __half*       __restrict__ y) {
    int w    = (int)(((size_t)blockIdx.x * blockDim.x + threadIdx.x) >> 5);
    int lane = threadIdx.x & 31;
    if (w >= N_NODES) return;
    int s = __ldg(row_ptr + w);
    int e = __ldg(row_ptr + w + 1);
    int half = lane >> 4;
    int sub  = lane & 15;

    float4 acc = row_accumulate(edges, x, s, e, half, sub);

    if (half == 0) {
        __half2 lo = __float22half2_rn(make_float2(acc.x, acc.y));
        __half2 hi = __float22half2_rn(make_float2(acc.z, acc.w));
        uint2 d;
        d.x = *(const unsigned int*)&lo;
        d.y = *(const unsigned int*)&hi;
        ((uint2*)(y + (size_t)w * DIM))[sub] = d;
    }
}

// layer 3 fused with final: out = 0.25*(emb0_fp32 + h1 + h2 + A*h2)
__global__ void __launch_bounds__(256)
spmm_final_kernel(const int*    __restrict__ row_ptr,
                  const int2*   __restrict__ edges,
                  const __half* __restrict__ x,     // = h2
                  const __half* __restrict__ h1,
                  const float*  __restrict__ ue,
                  const float*  __restrict__ ie,
                  float*        __restrict__ out) {
    int w    = (int)(((size_t)blockIdx.x * blockDim.x + threadIdx.x) >> 5);
    int lane = threadIdx.x & 31;
    if (w >= N_NODES) return;
    int s = __ldg(row_ptr + w);
    int e = __ldg(row_ptr + w + 1);
    int half = lane >> 4;
    int sub  = lane & 15;

    float4 acc = row_accumulate(edges, x, s, e, half, sub);

    if (half == 0) {
        const float* src = (w < NUM_USERS) ? (ue + (size_t)w * DIM)
                                           : (ie + (size_t)(w - NUM_USERS) * DIM);
        float4 e0 = __ldg((const float4*)src + sub);
        uint2 d1 = __ldg((const uint2*)(h1 + (size_t)w * DIM) + sub);
        uint2 d2 = __ldg((const uint2*)(x  + (size_t)w * DIM) + sub);
        float2 a0 = __half22float2(*(const __half2*)&d1.x);
        float2 a1 = __half22float2(*(const __half2*)&d1.y);
        float2 b0 = __half22float2(*(const __half2*)&d2.x);
        float2 b1 = __half22float2(*(const __half2*)&d2.y);
        float4 o;
        o.x = 0.25f * (e0.x + a0.x + b0.x + acc.x);
        o.y = 0.25f * (e0.y + a0.y + b0.y + acc.y);
        o.z = 0.25f * (e0.z + a1.x + b1.x + acc.z);
        o.w = 0.25f * (e0.w + a1.y + b1.y + acc.w);
        ((float4*)(out + (size_t)w * DIM))[sub] = o;
    }
}

// ---------------------------------------------------------------------------
// launch
// ---------------------------------------------------------------------------
extern "C" void kernel_launch(void* const* d_in, const int* in_sizes, int n_in,
                              void* d_out, int out_size) {
    const float* ue   = (const float*)d_in[0];
    const float* ie   = (const float*)d_in[1];
    const float* vals = (const float*)d_in[2];
    const int*   rows = (const int*)d_in[3];
    const int*   cols = (const int*)d_in[4];
    float* out = (float*)d_out;

    __half *h0, *h1, *h2;
    int2* edges;
    int *cnt, *row_ptr, *tile_status;
    cudaGetSymbolAddress((void**)&h0, g_h0);
    cudaGetSymbolAddress((void**)&h1, g_h1);
    cudaGetSymbolAddress((void**)&h2, g_h2);
    cudaGetSymbolAddress((void**)&edges, g_edges);
    cudaGetSymbolAddress((void**)&cnt, g_cnt);
    cudaGetSymbolAddress((void**)&row_ptr, g_row_ptr);
    cudaGetSymbolAddress((void**)&tile_status, g_tile_status);

    const int TPB = 256;
    const size_t nf4 = (size_t)N_NODES * DIM / 4;           // 4.8M float4s
    const int grid_f4   = (int)((nf4 + TPB - 1) / TPB);
    const int grid_sc4  = (NNZ / 4 + TPB - 1) / TPB;
    const size_t spmm_threads = (size_t)N_NODES * 32;       // warp per row
    const int grid_spmm = (int)((spmm_threads + TPB - 1) / TPB);

    // reset counters/status (memset nodes, not kernel launches)
    cudaMemsetAsync(cnt, 0, N_NODES * sizeof(int));
    cudaMemsetAsync(tile_status, 0, NB_SCAN * sizeof(int));

    // launch 0: h0 convert + row histogram (fused)
    init_hist_kernel<<<grid_f4, TPB>>>(ue, ie, h0, rows, cnt);
    // launch 1: single-pass scan -> row_ptr
    scan_rowptr_kernel<<<NB_SCAN, SCAN_TPB>>>(cnt, row_ptr, tile_status);
    // launch 2: permute edges into CSR order
    scatter_sort_kernel<<<grid_sc4, TPB>>>(vals, rows, cols, row_ptr,
                                           cnt, edges);
    // launches 3-5: the three SpMM layers (launch 3 = ncu window)
    spmm_h_kernel<<<grid_spmm, TPB>>>(row_ptr, edges, h0, h1);
    spmm_h_kernel<<<grid_spmm, TPB>>>(row_ptr, edges, h1, h2);
    spmm_final_kernel<<<grid_spmm, TPB>>>(row_ptr, edges, h2, h1, ue, ie, out);
}